// round 6
// baseline (speedup 1.0000x reference)
#include <cuda_runtime.h>
#include <math.h>

#define HIDDEN 640
#define ATTN   128
#define LN_EPS 1e-5f
#define WARPS  8          // warps per CTA in main kernel (256 threads)
#define CHUNKS 64         // chunks per batch (grid.x of main kernel)
#define GSPLIT 8          // k0 split-K groups
#define APERG  (ATTN / GSPLIT)   // 16
#define CSPLIT 8          // k2a split groups
#define CPG    (CHUNKS / CSPLIT) // 8 chunks per k2a1 CTA
#define MAXB   32
#define BSLICE 16         // batches handled per k2b z-slice (smem sizing)
#define MAXC   128
#define PSTRIDE (HIDDEN + 2)   // per-partial: m, Z, s[640]

// ---- scratch (no allocation allowed) ----
__device__ float g_wpart[MAXB * GSPLIT * HIDDEN];
__device__ float g_w[MAXB * HIDDEN];
__device__ float g_part[(size_t)MAXB * MAXC * PSTRIDE];
__device__ float g_sbpart[MAXB * CSPLIT * HIDDEN];
__device__ float g_sb[MAXB * HIDDEN];     // normalized pooled-X per batch
__device__ float g_pool[MAXB * HIDDEN];   // pooled after Wv GEMV

// ============================================================
// Kernel 0: split-K partial of w[b,h] = scale * sum_a q[b,a] * Wk[a,h].
// grid(B, GSPLIT), block(640).
// ============================================================
__global__ void __launch_bounds__(HIDDEN)
k0_make_w(const float* __restrict__ pos,
          const float* __restrict__ Wq,
          const float* __restrict__ Wk)
{
    __shared__ float ps[HIDDEN];
    __shared__ float qs[APERG];
    const int b    = blockIdx.x;
    const int g    = blockIdx.y;
    const int tid  = threadIdx.x;
    const int wid  = tid >> 5;
    const int lane = tid & 31;
    const int a0   = g * APERG;

    ps[tid] = pos[b * HIDDEN + tid];
    __syncthreads();

    if (wid < APERG) {
        const float4* ps4 = (const float4*)ps;
        const float4* row = (const float4*)(Wq + (size_t)(a0 + wid) * HIDDEN);
        float d = 0.f;
        #pragma unroll
        for (int j = 0; j < 5; j++) {
            const float4 r = row[lane + 32 * j];
            const float4 p = ps4[lane + 32 * j];
            d = fmaf(r.x, p.x, d);
            d = fmaf(r.y, p.y, d);
            d = fmaf(r.z, p.z, d);
            d = fmaf(r.w, p.w, d);
        }
        #pragma unroll
        for (int off = 16; off > 0; off >>= 1)
            d += __shfl_xor_sync(0xffffffffu, d, off);
        if (lane == 0) qs[wid] = d;
    }
    __syncthreads();

    const float scale = rsqrtf((float)ATTN);
    float s = 0.f;
    #pragma unroll
    for (int a = 0; a < APERG; a++)
        s = fmaf(qs[a], Wk[(size_t)(a0 + a) * HIDDEN + tid], s);
    g_wpart[((size_t)b * GSPLIT + g) * HIDDEN + tid] = s * scale;
}

// ============================================================
// Kernel 0b: reduce the GSPLIT partials once. grid(B), block(640).
// ============================================================
__global__ void __launch_bounds__(HIDDEN)
k0b_reduce()
{
    const int b   = blockIdx.x;
    const int tid = threadIdx.x;
    float s = 0.f;
    #pragma unroll
    for (int g = 0; g < GSPLIT; g++)
        s += g_wpart[((size_t)b * GSPLIT + g) * HIDDEN + tid];
    g_w[b * HIDDEN + tid] = s;
}

// ============================================================
// Kernel 1: streaming pass over X with online softmax, 2 tokens/warp-iter.
// grid(CHUNKS, B), block(256) = 8 warps.
// ============================================================
__global__ void __launch_bounds__(WARPS * 32)
k1_stream(const float* __restrict__ X, int N, int chunk)
{
    const int b    = blockIdx.y;
    const int c    = blockIdx.x;
    const int tid  = threadIdx.x;
    const int wid  = tid >> 5;
    const int lane = tid & 31;

    float4 w4[5];
    {
        const float4* wb4 = (const float4*)(g_w + b * HIDDEN);
        #pragma unroll
        for (int j = 0; j < 5; j++) w4[j] = wb4[lane + 32 * j];
    }

    const int t0 = c * chunk;
    const int t1 = min(N, t0 + chunk);

    float m = -1e30f, Z = 0.f;
    float4 acc[5];
    #pragma unroll
    for (int j = 0; j < 5; j++) acc[j] = make_float4(0.f, 0.f, 0.f, 0.f);

    for (int t = t0 + 2 * wid; t < t1; t += 2 * WARPS) {
        const bool two = (t + 1 < t1);
        const float4* row0 = (const float4*)(X + ((size_t)b * N + t) * HIDDEN);
        const float4* row1 = (const float4*)(X + ((size_t)b * N + (two ? t + 1 : t)) * HIDDEN);

        float4 r0[5], r1[5];
        #pragma unroll
        for (int j = 0; j < 5; j++) r0[j] = __ldcs(row0 + lane + 32 * j);
        #pragma unroll
        for (int j = 0; j < 5; j++) r1[j] = __ldcs(row1 + lane + 32 * j);

        float d0 = 0.f, d1 = 0.f;
        #pragma unroll
        for (int j = 0; j < 5; j++) {
            d0 = fmaf(r0[j].x, w4[j].x, d0); d1 = fmaf(r1[j].x, w4[j].x, d1);
            d0 = fmaf(r0[j].y, w4[j].y, d0); d1 = fmaf(r1[j].y, w4[j].y, d1);
            d0 = fmaf(r0[j].z, w4[j].z, d0); d1 = fmaf(r1[j].z, w4[j].z, d1);
            d0 = fmaf(r0[j].w, w4[j].w, d0); d1 = fmaf(r1[j].w, w4[j].w, d1);
        }
        #pragma unroll
        for (int off = 16; off > 0; off >>= 1) {
            d0 += __shfl_xor_sync(0xffffffffu, d0, off);
            d1 += __shfl_xor_sync(0xffffffffu, d1, off);
        }

        {
            float p;
            if (d0 > m) {
                const float f = __expf(m - d0);
                Z *= f;
                #pragma unroll
                for (int j = 0; j < 5; j++) {
                    acc[j].x *= f; acc[j].y *= f; acc[j].z *= f; acc[j].w *= f;
                }
                m = d0; p = 1.0f;
            } else p = __expf(d0 - m);
            Z += p;
            #pragma unroll
            for (int j = 0; j < 5; j++) {
                acc[j].x = fmaf(p, r0[j].x, acc[j].x);
                acc[j].y = fmaf(p, r0[j].y, acc[j].y);
                acc[j].z = fmaf(p, r0[j].z, acc[j].z);
                acc[j].w = fmaf(p, r0[j].w, acc[j].w);
            }
        }
        if (two) {
            float p;
            if (d1 > m) {
                const float f = __expf(m - d1);
                Z *= f;
                #pragma unroll
                for (int j = 0; j < 5; j++) {
                    acc[j].x *= f; acc[j].y *= f; acc[j].z *= f; acc[j].w *= f;
                }
                m = d1; p = 1.0f;
            } else p = __expf(d1 - m);
            Z += p;
            #pragma unroll
            for (int j = 0; j < 5; j++) {
                acc[j].x = fmaf(p, r1[j].x, acc[j].x);
                acc[j].y = fmaf(p, r1[j].y, acc[j].y);
                acc[j].z = fmaf(p, r1[j].z, acc[j].z);
                acc[j].w = fmaf(p, r1[j].w, acc[j].w);
            }
        }
    }

    // ---- CTA combine across 8 warps ----
    __shared__ float sm_s[WARPS][HIDDEN];
    __shared__ float sm_m[WARPS], sm_Z[WARPS], sm_f[WARPS];

    {
        float4* srow = (float4*)sm_s[wid];
        #pragma unroll
        for (int j = 0; j < 5; j++) srow[lane + 32 * j] = acc[j];
        if (lane == 0) { sm_m[wid] = m; sm_Z[wid] = Z; }
    }
    __syncthreads();

    if (tid == 0) {
        float M = -1e30f;
        #pragma unroll
        for (int w = 0; w < WARPS; w++) M = fmaxf(M, sm_m[w]);
        float Zt = 0.f;
        #pragma unroll
        for (int w = 0; w < WARPS; w++) {
            const float f = __expf(sm_m[w] - M);
            sm_f[w] = f;
            Zt += f * sm_Z[w];
        }
        float* out = g_part + ((size_t)b * MAXC + c) * PSTRIDE;
        out[0] = M; out[1] = Zt;
    }
    __syncthreads();

    float* out = g_part + ((size_t)b * MAXC + c) * PSTRIDE;
    for (int h = tid; h < HIDDEN; h += WARPS * 32) {
        float s = 0.f;
        #pragma unroll
        for (int w = 0; w < WARPS; w++) s = fmaf(sm_f[w], sm_s[w][h], s);
        out[2 + h] = s;
    }
}

// ============================================================
// Kernel 2a1: per-(b,cs) partial combine of CPG chunks (un-normalized,
// referenced to the GLOBAL max M). grid(B, CSPLIT), block(640).
// ============================================================
__global__ void __launch_bounds__(HIDDEN)
k2a1_partial(int C)
{
    const int b    = blockIdx.x;
    const int cs   = blockIdx.y;
    const int tid  = threadIdx.x;
    const int wid  = tid >> 5;
    const int lane = tid & 31;

    __shared__ float sf[CPG];
    __shared__ float sM;

    const float* pbase = g_part + (size_t)b * MAXC * PSTRIDE;

    // warp 0: global max over all C chunk maxima, then f for this group's chunks
    if (wid == 0) {
        float m0 = -1e30f, m1 = -1e30f;
        if (lane < C)      m0 = pbase[(size_t)lane * PSTRIDE];
        if (lane + 32 < C) m1 = pbase[(size_t)(lane + 32) * PSTRIDE];
        float M = fmaxf(m0, m1);
        #pragma unroll
        for (int off = 16; off > 0; off >>= 1)
            M = fmaxf(M, __shfl_xor_sync(0xffffffffu, M, off));
        if (lane == 0) sM = M;
        if (lane < CPG) {
            const float mc = pbase[(size_t)(cs * CPG + lane) * PSTRIDE];
            sf[lane] = __expf(mc - M);
        }
    }
    __syncthreads();

    float s = 0.f;
    #pragma unroll
    for (int c = 0; c < CPG; c++)
        s = fmaf(sf[c], pbase[(size_t)(cs * CPG + c) * PSTRIDE + 2 + tid], s);
    g_sbpart[((size_t)b * CSPLIT + cs) * HIDDEN + tid] = s;
}

// ============================================================
// Kernel 2a2: reduce CSPLIT partials, normalize by Z. grid(B), block(640).
// ============================================================
__global__ void __launch_bounds__(HIDDEN)
k2a2_reduce(int C)
{
    const int b    = blockIdx.x;
    const int tid  = threadIdx.x;
    const int wid  = tid >> 5;
    const int lane = tid & 31;

    __shared__ float sZ;

    const float* pbase = g_part + (size_t)b * MAXC * PSTRIDE;

    // warp 0: global M and total Z from chunk stats (L2-hit, tiny)
    if (wid == 0) {
        float m0 = -1e30f, m1 = -1e30f;
        if (lane < C)      m0 = pbase[(size_t)lane * PSTRIDE];
        if (lane + 32 < C) m1 = pbase[(size_t)(lane + 32) * PSTRIDE];
        float M = fmaxf(m0, m1);
        #pragma unroll
        for (int off = 16; off > 0; off >>= 1)
            M = fmaxf(M, __shfl_xor_sync(0xffffffffu, M, off));

        float z = 0.f;
        if (lane < C)      z += __expf(m0 - M) * pbase[(size_t)lane * PSTRIDE + 1];
        if (lane + 32 < C) z += __expf(m1 - M) * pbase[(size_t)(lane + 32) * PSTRIDE + 1];
        #pragma unroll
        for (int off = 16; off > 0; off >>= 1)
            z += __shfl_xor_sync(0xffffffffu, z, off);
        if (lane == 0) sZ = z;
    }
    __syncthreads();

    const float invZ = 1.0f / sZ;
    float s = 0.f;
    #pragma unroll
    for (int g = 0; g < CSPLIT; g++)
        s += g_sbpart[((size_t)b * CSPLIT + g) * HIDDEN + tid];
    g_sb[b * HIDDEN + tid] = s * invZ;
}

// ============================================================
// Kernel 2b: pooled[b][v] = g_sb[b] . Wv[v]  for all b at once.
// grid(HIDDEN/8, 1, ceil(B/BSLICE)), block(256) = 8 warps, warp-per-row.
// ============================================================
__global__ void __launch_bounds__(256)
k2b_gemv(const float* __restrict__ Wv, int B)
{
    __shared__ float sb_sm[BSLICE * HIDDEN];   // 40 KB

    const int tid  = threadIdx.x;
    const int wid  = tid >> 5;
    const int lane = tid & 31;
    const int b0   = blockIdx.z * BSLICE;
    const int nb   = min(BSLICE, B - b0);
    const int v    = blockIdx.x * 8 + wid;

    for (int i = tid; i < nb * HIDDEN; i += 256)
        sb_sm[i] = g_sb[(size_t)b0 * HIDDEN + i];
    __syncthreads();

    float4 r[5];
    {
        const float4* wr = (const float4*)(Wv + (size_t)v * HIDDEN);
        #pragma unroll
        for (int j = 0; j < 5; j++) r[j] = wr[lane + 32 * j];
    }

    for (int b = 0; b < nb; b += 2) {
        const bool two = (b + 1 < nb);
        const float4* s0 = (const float4*)(sb_sm + (size_t)b * HIDDEN);
        const float4* s1 = (const float4*)(sb_sm + (size_t)(two ? b + 1 : b) * HIDDEN);
        float d0 = 0.f, d1 = 0.f;
        #pragma unroll
        for (int j = 0; j < 5; j++) {
            const float4 a0 = s0[lane + 32 * j];
            const float4 a1 = s1[lane + 32 * j];
            d0 = fmaf(r[j].x, a0.x, d0); d1 = fmaf(r[j].x, a1.x, d1);
            d0 = fmaf(r[j].y, a0.y, d0); d1 = fmaf(r[j].y, a1.y, d1);
            d0 = fmaf(r[j].z, a0.z, d0); d1 = fmaf(r[j].z, a1.z, d1);
            d0 = fmaf(r[j].w, a0.w, d0); d1 = fmaf(r[j].w, a1.w, d1);
        }
        #pragma unroll
        for (int off = 16; off > 0; off >>= 1) {
            d0 += __shfl_xor_sync(0xffffffffu, d0, off);
            d1 += __shfl_xor_sync(0xffffffffu, d1, off);
        }
        if (lane == 0) {
            g_pool[(size_t)(b0 + b) * HIDDEN + v] = d0;
            if (two) g_pool[(size_t)(b0 + b + 1) * HIDDEN + v] = d1;
        }
    }
}

// ============================================================
// Kernel 2c: LayerNorm over pooled, write output. grid(B), block(640).
// ============================================================
__global__ void __launch_bounds__(HIDDEN)
k2c_ln(const float* __restrict__ gamma,
       const float* __restrict__ beta,
       float* __restrict__ out)
{
    const int b    = blockIdx.x;
    const int tid  = threadIdx.x;
    const int wid  = tid >> 5;
    const int lane = tid & 31;

    const float x = g_pool[(size_t)b * HIDDEN + tid];

    __shared__ float rs[HIDDEN / 32], rq[HIDDEN / 32], smu, srstd;
    {
        float s = x, q = x * x;
        #pragma unroll
        for (int off = 16; off > 0; off >>= 1) {
            s += __shfl_xor_sync(0xffffffffu, s, off);
            q += __shfl_xor_sync(0xffffffffu, q, off);
        }
        if (lane == 0) { rs[wid] = s; rq[wid] = q; }
    }
    __syncthreads();
    if (tid == 0) {
        float s = 0.f, q = 0.f;
        #pragma unroll
        for (int w = 0; w < HIDDEN / 32; w++) { s += rs[w]; q += rq[w]; }
        const float mu = s / (float)HIDDEN;
        const float var = q / (float)HIDDEN - mu * mu;
        smu = mu;
        srstd = rsqrtf(var + LN_EPS);
    }
    __syncthreads();

    out[(size_t)b * HIDDEN + tid] = (x - smu) * srstd * gamma[tid] + beta[tid];
}

// ============================================================
extern "C" void kernel_launch(void* const* d_in, const int* in_sizes, int n_in,
                              void* d_out, int out_size)
{
    const float* X     = (const float*)d_in[0];
    const float* pos   = (const float*)d_in[1];
    const float* Wq    = (const float*)d_in[2];
    const float* Wk    = (const float*)d_in[3];
    const float* Wv    = (const float*)d_in[4];
    const float* gamma = (const float*)d_in[5];
    const float* beta  = (const float*)d_in[6];
    float* out = (float*)d_out;

    const int B = in_sizes[1] / HIDDEN;
    const int N = in_sizes[0] / (B * HIDDEN);
    const int C = CHUNKS;
    const int chunk = (N + C - 1) / C;

    dim3 g0(B, GSPLIT);
    k0_make_w<<<g0, HIDDEN>>>(pos, Wq, Wk);
    k0b_reduce<<<B, HIDDEN>>>();
    dim3 g1(C, B);
    k1_stream<<<g1, WARPS * 32>>>(X, N, chunk);
    dim3 g2a(B, CSPLIT);
    k2a1_partial<<<g2a, HIDDEN>>>(C);
    k2a2_reduce<<<B, HIDDEN>>>(C);
    dim3 g2b(HIDDEN / 8, 1, (B + BSLICE - 1) / BSLICE);
    k2b_gemv<<<g2b, 256>>>(Wv, B);
    k2c_ln<<<B, HIDDEN>>>(gamma, beta, out);
}

// round 7
// speedup vs baseline: 1.0038x; 1.0038x over previous
#include <cuda_runtime.h>
#include <math.h>

#define HIDDEN 640
#define ATTN   128
#define LN_EPS 1e-5f
#define WARPS  8          // warps per CTA in main kernel (256 threads)
#define CHUNKS 64         // chunks per batch (grid.x of main kernel)
#define GSPLIT 8          // k0 split-K groups
#define APERG  (ATTN / GSPLIT)   // 16
#define CSPLIT 8          // k2a split groups
#define CPG    (CHUNKS / CSPLIT) // 8 chunks per k2a1 CTA
#define MAXB   32
#define BSLICE 16         // batches handled per k2b z-slice (smem sizing)
#define MAXC   128
#define PSTRIDE (HIDDEN + 2)   // per-partial: m, Z, s[640]

// ---- scratch (no allocation allowed) ----
__device__ float g_wpart[MAXB * GSPLIT * HIDDEN];
__device__ float g_w[MAXB * HIDDEN];
__device__ float g_part[(size_t)MAXB * MAXC * PSTRIDE];
__device__ float g_sbpart[MAXB * CSPLIT * HIDDEN];
__device__ float g_sb[MAXB * HIDDEN];     // normalized pooled-X per batch
__device__ float g_pool[MAXB * HIDDEN];   // pooled after Wv GEMV

// ============================================================
// Kernel 0: split-K partial of w[b,h] = scale * sum_a q[b,a] * Wk[a,h].
// grid(B, GSPLIT), block(640).
// ============================================================
__global__ void __launch_bounds__(HIDDEN)
k0_make_w(const float* __restrict__ pos,
          const float* __restrict__ Wq,
          const float* __restrict__ Wk)
{
    __shared__ float ps[HIDDEN];
    __shared__ float qs[APERG];
    const int b    = blockIdx.x;
    const int g    = blockIdx.y;
    const int tid  = threadIdx.x;
    const int wid  = tid >> 5;
    const int lane = tid & 31;
    const int a0   = g * APERG;

    ps[tid] = pos[b * HIDDEN + tid];
    __syncthreads();

    if (wid < APERG) {
        const float4* ps4 = (const float4*)ps;
        const float4* row = (const float4*)(Wq + (size_t)(a0 + wid) * HIDDEN);
        float d = 0.f;
        #pragma unroll
        for (int j = 0; j < 5; j++) {
            const float4 r = row[lane + 32 * j];
            const float4 p = ps4[lane + 32 * j];
            d = fmaf(r.x, p.x, d);
            d = fmaf(r.y, p.y, d);
            d = fmaf(r.z, p.z, d);
            d = fmaf(r.w, p.w, d);
        }
        #pragma unroll
        for (int off = 16; off > 0; off >>= 1)
            d += __shfl_xor_sync(0xffffffffu, d, off);
        if (lane == 0) qs[wid] = d;
    }
    __syncthreads();

    const float scale = rsqrtf((float)ATTN);
    float s = 0.f;
    #pragma unroll
    for (int a = 0; a < APERG; a++)
        s = fmaf(qs[a], Wk[(size_t)(a0 + a) * HIDDEN + tid], s);
    g_wpart[((size_t)b * GSPLIT + g) * HIDDEN + tid] = s * scale;
}

// ============================================================
// Kernel 0b: reduce the GSPLIT partials once. grid(B), block(640).
// ============================================================
__global__ void __launch_bounds__(HIDDEN)
k0b_reduce()
{
    const int b   = blockIdx.x;
    const int tid = threadIdx.x;
    float s = 0.f;
    #pragma unroll
    for (int g = 0; g < GSPLIT; g++)
        s += g_wpart[((size_t)b * GSPLIT + g) * HIDDEN + tid];
    g_w[b * HIDDEN + tid] = s;
}

// ============================================================
// Kernel 1: streaming pass over X with online softmax, 2 tokens/warp-iter.
// grid(CHUNKS, B), block(256) = 8 warps.
// ============================================================
__global__ void __launch_bounds__(WARPS * 32)
k1_stream(const float* __restrict__ X, int N, int chunk)
{
    const int b    = blockIdx.y;
    const int c    = blockIdx.x;
    const int tid  = threadIdx.x;
    const int wid  = tid >> 5;
    const int lane = tid & 31;

    float4 w4[5];
    {
        const float4* wb4 = (const float4*)(g_w + b * HIDDEN);
        #pragma unroll
        for (int j = 0; j < 5; j++) w4[j] = wb4[lane + 32 * j];
    }

    const int t0 = c * chunk;
    const int t1 = min(N, t0 + chunk);

    float m = -1e30f, Z = 0.f;
    float4 acc[5];
    #pragma unroll
    for (int j = 0; j < 5; j++) acc[j] = make_float4(0.f, 0.f, 0.f, 0.f);

    for (int t = t0 + 2 * wid; t < t1; t += 2 * WARPS) {
        const bool two = (t + 1 < t1);
        const float4* row0 = (const float4*)(X + ((size_t)b * N + t) * HIDDEN);
        const float4* row1 = (const float4*)(X + ((size_t)b * N + (two ? t + 1 : t)) * HIDDEN);

        float4 r0[5], r1[5];
        #pragma unroll
        for (int j = 0; j < 5; j++) r0[j] = __ldcs(row0 + lane + 32 * j);
        #pragma unroll
        for (int j = 0; j < 5; j++) r1[j] = __ldcs(row1 + lane + 32 * j);

        float d0 = 0.f, d1 = 0.f;
        #pragma unroll
        for (int j = 0; j < 5; j++) {
            d0 = fmaf(r0[j].x, w4[j].x, d0); d1 = fmaf(r1[j].x, w4[j].x, d1);
            d0 = fmaf(r0[j].y, w4[j].y, d0); d1 = fmaf(r1[j].y, w4[j].y, d1);
            d0 = fmaf(r0[j].z, w4[j].z, d0); d1 = fmaf(r1[j].z, w4[j].z, d1);
            d0 = fmaf(r0[j].w, w4[j].w, d0); d1 = fmaf(r1[j].w, w4[j].w, d1);
        }
        #pragma unroll
        for (int off = 16; off > 0; off >>= 1) {
            d0 += __shfl_xor_sync(0xffffffffu, d0, off);
            d1 += __shfl_xor_sync(0xffffffffu, d1, off);
        }

        {
            float p;
            if (d0 > m) {
                const float f = __expf(m - d0);
                Z *= f;
                #pragma unroll
                for (int j = 0; j < 5; j++) {
                    acc[j].x *= f; acc[j].y *= f; acc[j].z *= f; acc[j].w *= f;
                }
                m = d0; p = 1.0f;
            } else p = __expf(d0 - m);
            Z += p;
            #pragma unroll
            for (int j = 0; j < 5; j++) {
                acc[j].x = fmaf(p, r0[j].x, acc[j].x);
                acc[j].y = fmaf(p, r0[j].y, acc[j].y);
                acc[j].z = fmaf(p, r0[j].z, acc[j].z);
                acc[j].w = fmaf(p, r0[j].w, acc[j].w);
            }
        }
        if (two) {
            float p;
            if (d1 > m) {
                const float f = __expf(m - d1);
                Z *= f;
                #pragma unroll
                for (int j = 0; j < 5; j++) {
                    acc[j].x *= f; acc[j].y *= f; acc[j].z *= f; acc[j].w *= f;
                }
                m = d1; p = 1.0f;
            } else p = __expf(d1 - m);
            Z += p;
            #pragma unroll
            for (int j = 0; j < 5; j++) {
                acc[j].x = fmaf(p, r1[j].x, acc[j].x);
                acc[j].y = fmaf(p, r1[j].y, acc[j].y);
                acc[j].z = fmaf(p, r1[j].z, acc[j].z);
                acc[j].w = fmaf(p, r1[j].w, acc[j].w);
            }
        }
    }

    // ---- CTA combine across 8 warps ----
    __shared__ float sm_s[WARPS][HIDDEN];
    __shared__ float sm_m[WARPS], sm_Z[WARPS], sm_f[WARPS];

    {
        float4* srow = (float4*)sm_s[wid];
        #pragma unroll
        for (int j = 0; j < 5; j++) srow[lane + 32 * j] = acc[j];
        if (lane == 0) { sm_m[wid] = m; sm_Z[wid] = Z; }
    }
    __syncthreads();

    if (tid == 0) {
        float M = -1e30f;
        #pragma unroll
        for (int w = 0; w < WARPS; w++) M = fmaxf(M, sm_m[w]);
        float Zt = 0.f;
        #pragma unroll
        for (int w = 0; w < WARPS; w++) {
            const float f = __expf(sm_m[w] - M);
            sm_f[w] = f;
            Zt += f * sm_Z[w];
        }
        float* out = g_part + ((size_t)b * MAXC + c) * PSTRIDE;
        out[0] = M; out[1] = Zt;
    }
    __syncthreads();

    float* out = g_part + ((size_t)b * MAXC + c) * PSTRIDE;
    for (int h = tid; h < HIDDEN; h += WARPS * 32) {
        float s = 0.f;
        #pragma unroll
        for (int w = 0; w < WARPS; w++) s = fmaf(sm_f[w], sm_s[w][h], s);
        out[2 + h] = s;
    }
}

// ============================================================
// Kernel 2a1: per-(b,cs) partial combine of CPG chunks (un-normalized,
// referenced to the GLOBAL max M). grid(B, CSPLIT), block(640).
// ============================================================
__global__ void __launch_bounds__(HIDDEN)
k2a1_partial(int C)
{
    const int b    = blockIdx.x;
    const int cs   = blockIdx.y;
    const int tid  = threadIdx.x;
    const int wid  = tid >> 5;
    const int lane = tid & 31;

    __shared__ float sf[CPG];
    __shared__ float sM;

    const float* pbase = g_part + (size_t)b * MAXC * PSTRIDE;

    // warp 0: global max over all C chunk maxima, then f for this group's chunks
    if (wid == 0) {
        float m0 = -1e30f, m1 = -1e30f;
        if (lane < C)      m0 = pbase[(size_t)lane * PSTRIDE];
        if (lane + 32 < C) m1 = pbase[(size_t)(lane + 32) * PSTRIDE];
        float M = fmaxf(m0, m1);
        #pragma unroll
        for (int off = 16; off > 0; off >>= 1)
            M = fmaxf(M, __shfl_xor_sync(0xffffffffu, M, off));
        if (lane == 0) sM = M;
        if (lane < CPG) {
            const float mc = pbase[(size_t)(cs * CPG + lane) * PSTRIDE];
            sf[lane] = __expf(mc - M);
        }
    }
    __syncthreads();

    float s = 0.f;
    #pragma unroll
    for (int c = 0; c < CPG; c++)
        s = fmaf(sf[c], pbase[(size_t)(cs * CPG + c) * PSTRIDE + 2 + tid], s);
    g_sbpart[((size_t)b * CSPLIT + cs) * HIDDEN + tid] = s;
}

// ============================================================
// Kernel 2a2: reduce CSPLIT partials, normalize by Z. grid(B), block(640).
// ============================================================
__global__ void __launch_bounds__(HIDDEN)
k2a2_reduce(int C)
{
    const int b    = blockIdx.x;
    const int tid  = threadIdx.x;
    const int wid  = tid >> 5;
    const int lane = tid & 31;

    __shared__ float sZ;

    const float* pbase = g_part + (size_t)b * MAXC * PSTRIDE;

    // warp 0: global M and total Z from chunk stats (L2-hit, tiny)
    if (wid == 0) {
        float m0 = -1e30f, m1 = -1e30f;
        if (lane < C)      m0 = pbase[(size_t)lane * PSTRIDE];
        if (lane + 32 < C) m1 = pbase[(size_t)(lane + 32) * PSTRIDE];
        float M = fmaxf(m0, m1);
        #pragma unroll
        for (int off = 16; off > 0; off >>= 1)
            M = fmaxf(M, __shfl_xor_sync(0xffffffffu, M, off));

        float z = 0.f;
        if (lane < C)      z += __expf(m0 - M) * pbase[(size_t)lane * PSTRIDE + 1];
        if (lane + 32 < C) z += __expf(m1 - M) * pbase[(size_t)(lane + 32) * PSTRIDE + 1];
        #pragma unroll
        for (int off = 16; off > 0; off >>= 1)
            z += __shfl_xor_sync(0xffffffffu, z, off);
        if (lane == 0) sZ = z;
    }
    __syncthreads();

    const float invZ = 1.0f / sZ;
    float s = 0.f;
    #pragma unroll
    for (int g = 0; g < CSPLIT; g++)
        s += g_sbpart[((size_t)b * CSPLIT + g) * HIDDEN + tid];
    g_sb[b * HIDDEN + tid] = s * invZ;
}

// ============================================================
// Kernel 2b: pooled[b][v] = g_sb[b] . Wv[v]  for all b at once.
// grid(HIDDEN/8, 1, ceil(B/BSLICE)), block(256) = 8 warps, warp-per-row.
// ============================================================
__global__ void __launch_bounds__(256)
k2b_gemv(const float* __restrict__ Wv, int B)
{
    __shared__ float sb_sm[BSLICE * HIDDEN];   // 40 KB

    const int tid  = threadIdx.x;
    const int wid  = tid >> 5;
    const int lane = tid & 31;
    const int b0   = blockIdx.z * BSLICE;
    const int nb   = min(BSLICE, B - b0);
    const int v    = blockIdx.x * 8 + wid;

    for (int i = tid; i < nb * HIDDEN; i += 256)
        sb_sm[i] = g_sb[(size_t)b0 * HIDDEN + i];
    __syncthreads();

    float4 r[5];
    {
        const float4* wr = (const float4*)(Wv + (size_t)v * HIDDEN);
        #pragma unroll
        for (int j = 0; j < 5; j++) r[j] = wr[lane + 32 * j];
    }

    for (int b = 0; b < nb; b += 2) {
        const bool two = (b + 1 < nb);
        const float4* s0 = (const float4*)(sb_sm + (size_t)b * HIDDEN);
        const float4* s1 = (const float4*)(sb_sm + (size_t)(two ? b + 1 : b) * HIDDEN);
        float d0 = 0.f, d1 = 0.f;
        #pragma unroll
        for (int j = 0; j < 5; j++) {
            const float4 a0 = s0[lane + 32 * j];
            const float4 a1 = s1[lane + 32 * j];
            d0 = fmaf(r[j].x, a0.x, d0); d1 = fmaf(r[j].x, a1.x, d1);
            d0 = fmaf(r[j].y, a0.y, d0); d1 = fmaf(r[j].y, a1.y, d1);
            d0 = fmaf(r[j].z, a0.z, d0); d1 = fmaf(r[j].z, a1.z, d1);
            d0 = fmaf(r[j].w, a0.w, d0); d1 = fmaf(r[j].w, a1.w, d1);
        }
        #pragma unroll
        for (int off = 16; off > 0; off >>= 1) {
            d0 += __shfl_xor_sync(0xffffffffu, d0, off);
            d1 += __shfl_xor_sync(0xffffffffu, d1, off);
        }
        if (lane == 0) {
            g_pool[(size_t)(b0 + b) * HIDDEN + v] = d0;
            if (two) g_pool[(size_t)(b0 + b + 1) * HIDDEN + v] = d1;
        }
    }
}

// ============================================================
// Kernel 2c: LayerNorm over pooled, write output. grid(B), block(640).
// ============================================================
__global__ void __launch_bounds__(HIDDEN)
k2c_ln(const float* __restrict__ gamma,
       const float* __restrict__ beta,
       float* __restrict__ out)
{
    const int b    = blockIdx.x;
    const int tid  = threadIdx.x;
    const int wid  = tid >> 5;
    const int lane = tid & 31;

    const float x = g_pool[(size_t)b * HIDDEN + tid];

    __shared__ float rs[HIDDEN / 32], rq[HIDDEN / 32], smu, srstd;
    {
        float s = x, q = x * x;
        #pragma unroll
        for (int off = 16; off > 0; off >>= 1) {
            s += __shfl_xor_sync(0xffffffffu, s, off);
            q += __shfl_xor_sync(0xffffffffu, q, off);
        }
        if (lane == 0) { rs[wid] = s; rq[wid] = q; }
    }
    __syncthreads();
    if (tid == 0) {
        float s = 0.f, q = 0.f;
        #pragma unroll
        for (int w = 0; w < HIDDEN / 32; w++) { s += rs[w]; q += rq[w]; }
        const float mu = s / (float)HIDDEN;
        const float var = q / (float)HIDDEN - mu * mu;
        smu = mu;
        srstd = rsqrtf(var + LN_EPS);
    }
    __syncthreads();

    out[(size_t)b * HIDDEN + tid] = (x - smu) * srstd * gamma[tid] + beta[tid];
}

// ============================================================
extern "C" void kernel_launch(void* const* d_in, const int* in_sizes, int n_in,
                              void* d_out, int out_size)
{
    const float* X     = (const float*)d_in[0];
    const float* pos   = (const float*)d_in[1];
    const float* Wq    = (const float*)d_in[2];
    const float* Wk    = (const float*)d_in[3];
    const float* Wv    = (const float*)d_in[4];
    const float* gamma = (const float*)d_in[5];
    const float* beta  = (const float*)d_in[6];
    float* out = (float*)d_out;

    const int B = in_sizes[1] / HIDDEN;
    const int N = in_sizes[0] / (B * HIDDEN);
    const int C = CHUNKS;
    const int chunk = (N + C - 1) / C;

    dim3 g0(B, GSPLIT);
    k0_make_w<<<g0, HIDDEN>>>(pos, Wq, Wk);
    k0b_reduce<<<B, HIDDEN>>>();
    dim3 g1(C, B);
    k1_stream<<<g1, WARPS * 32>>>(X, N, chunk);
    dim3 g2a(B, CSPLIT);
    k2a1_partial<<<g2a, HIDDEN>>>(C);
    k2a2_reduce<<<B, HIDDEN>>>(C);
    dim3 g2b(HIDDEN / 8, 1, (B + BSLICE - 1) / BSLICE);
    k2b_gemv<<<g2b, 256>>>(Wv, B);
    k2c_ln<<<B, HIDDEN>>>(gamma, beta, out);
}

// round 8
// speedup vs baseline: 1.0058x; 1.0020x over previous
#include <cuda_runtime.h>
#include <math.h>

#define HIDDEN 640
#define ATTN   128
#define LN_EPS 1e-5f
#define WARPS  8          // warps per CTA in main kernel (256 threads)
#define CHUNKS 64         // chunks per batch (grid.x of main kernel)
#define GSPLIT 8          // k0 split-K groups
#define APERG  (ATTN / GSPLIT)   // 16
#define CSPLIT 8          // k2a split groups
#define CPG    (CHUNKS / CSPLIT) // 8 chunks per k2a1 CTA
#define MAXB   32
#define BSLICE 16         // batches handled per k2b z-slice (smem sizing)
#define MAXC   128
#define PSTRIDE (HIDDEN + 2)   // per-partial: m, Z, s[640]

// ---- scratch (no allocation allowed) ----
__device__ float g_wpart[MAXB * GSPLIT * HIDDEN];
__device__ float g_w[MAXB * HIDDEN];
__device__ float g_part[(size_t)MAXB * MAXC * PSTRIDE];
__device__ float g_sbpart[MAXB * CSPLIT * HIDDEN];
__device__ float g_sb[MAXB * HIDDEN];     // normalized pooled-X per batch
__device__ float g_pool[MAXB * HIDDEN];   // pooled after Wv GEMV

// ============================================================
// Kernel 0: split-K partial of w[b,h] = scale * sum_a q[b,a] * Wk[a,h].
// grid(B, GSPLIT), block(640).
// ============================================================
__global__ void __launch_bounds__(HIDDEN)
k0_make_w(const float* __restrict__ pos,
          const float* __restrict__ Wq,
          const float* __restrict__ Wk)
{
    __shared__ float ps[HIDDEN];
    __shared__ float qs[APERG];
    const int b    = blockIdx.x;
    const int g    = blockIdx.y;
    const int tid  = threadIdx.x;
    const int wid  = tid >> 5;
    const int lane = tid & 31;
    const int a0   = g * APERG;

    ps[tid] = pos[b * HIDDEN + tid];
    __syncthreads();

    if (wid < APERG) {
        const float4* ps4 = (const float4*)ps;
        const float4* row = (const float4*)(Wq + (size_t)(a0 + wid) * HIDDEN);
        float d = 0.f;
        #pragma unroll
        for (int j = 0; j < 5; j++) {
            const float4 r = row[lane + 32 * j];
            const float4 p = ps4[lane + 32 * j];
            d = fmaf(r.x, p.x, d);
            d = fmaf(r.y, p.y, d);
            d = fmaf(r.z, p.z, d);
            d = fmaf(r.w, p.w, d);
        }
        #pragma unroll
        for (int off = 16; off > 0; off >>= 1)
            d += __shfl_xor_sync(0xffffffffu, d, off);
        if (lane == 0) qs[wid] = d;
    }
    __syncthreads();

    const float scale = rsqrtf((float)ATTN);
    float s = 0.f;
    #pragma unroll
    for (int a = 0; a < APERG; a++)
        s = fmaf(qs[a], Wk[(size_t)(a0 + a) * HIDDEN + tid], s);
    g_wpart[((size_t)b * GSPLIT + g) * HIDDEN + tid] = s * scale;
}

// ============================================================
// Kernel 0b: reduce the GSPLIT partials once. grid(B), block(640).
// ============================================================
__global__ void __launch_bounds__(HIDDEN)
k0b_reduce()
{
    const int b   = blockIdx.x;
    const int tid = threadIdx.x;
    float s = 0.f;
    #pragma unroll
    for (int g = 0; g < GSPLIT; g++)
        s += g_wpart[((size_t)b * GSPLIT + g) * HIDDEN + tid];
    g_w[b * HIDDEN + tid] = s;
}

// ============================================================
// Kernel 1: streaming pass over X with online softmax, 2 tokens/warp-iter.
// grid(CHUNKS, B), block(256) = 8 warps.
// ============================================================
__global__ void __launch_bounds__(WARPS * 32)
k1_stream(const float* __restrict__ X, int N, int chunk)
{
    const int b    = blockIdx.y;
    const int c    = blockIdx.x;
    const int tid  = threadIdx.x;
    const int wid  = tid >> 5;
    const int lane = tid & 31;

    float4 w4[5];
    {
        const float4* wb4 = (const float4*)(g_w + b * HIDDEN);
        #pragma unroll
        for (int j = 0; j < 5; j++) w4[j] = wb4[lane + 32 * j];
    }

    const int t0 = c * chunk;
    const int t1 = min(N, t0 + chunk);

    float m = -1e30f, Z = 0.f;
    float4 acc[5];
    #pragma unroll
    for (int j = 0; j < 5; j++) acc[j] = make_float4(0.f, 0.f, 0.f, 0.f);

    for (int t = t0 + 2 * wid; t < t1; t += 2 * WARPS) {
        const bool two = (t + 1 < t1);
        const float4* row0 = (const float4*)(X + ((size_t)b * N + t) * HIDDEN);
        const float4* row1 = (const float4*)(X + ((size_t)b * N + (two ? t + 1 : t)) * HIDDEN);

        float4 r0[5], r1[5];
        #pragma unroll
        for (int j = 0; j < 5; j++) r0[j] = __ldcs(row0 + lane + 32 * j);
        #pragma unroll
        for (int j = 0; j < 5; j++) r1[j] = __ldcs(row1 + lane + 32 * j);

        float d0 = 0.f, d1 = 0.f;
        #pragma unroll
        for (int j = 0; j < 5; j++) {
            d0 = fmaf(r0[j].x, w4[j].x, d0); d1 = fmaf(r1[j].x, w4[j].x, d1);
            d0 = fmaf(r0[j].y, w4[j].y, d0); d1 = fmaf(r1[j].y, w4[j].y, d1);
            d0 = fmaf(r0[j].z, w4[j].z, d0); d1 = fmaf(r1[j].z, w4[j].z, d1);
            d0 = fmaf(r0[j].w, w4[j].w, d0); d1 = fmaf(r1[j].w, w4[j].w, d1);
        }
        #pragma unroll
        for (int off = 16; off > 0; off >>= 1) {
            d0 += __shfl_xor_sync(0xffffffffu, d0, off);
            d1 += __shfl_xor_sync(0xffffffffu, d1, off);
        }

        {
            float p;
            if (d0 > m) {
                const float f = __expf(m - d0);
                Z *= f;
                #pragma unroll
                for (int j = 0; j < 5; j++) {
                    acc[j].x *= f; acc[j].y *= f; acc[j].z *= f; acc[j].w *= f;
                }
                m = d0; p = 1.0f;
            } else p = __expf(d0 - m);
            Z += p;
            #pragma unroll
            for (int j = 0; j < 5; j++) {
                acc[j].x = fmaf(p, r0[j].x, acc[j].x);
                acc[j].y = fmaf(p, r0[j].y, acc[j].y);
                acc[j].z = fmaf(p, r0[j].z, acc[j].z);
                acc[j].w = fmaf(p, r0[j].w, acc[j].w);
            }
        }
        if (two) {
            float p;
            if (d1 > m) {
                const float f = __expf(m - d1);
                Z *= f;
                #pragma unroll
                for (int j = 0; j < 5; j++) {
                    acc[j].x *= f; acc[j].y *= f; acc[j].z *= f; acc[j].w *= f;
                }
                m = d1; p = 1.0f;
            } else p = __expf(d1 - m);
            Z += p;
            #pragma unroll
            for (int j = 0; j < 5; j++) {
                acc[j].x = fmaf(p, r1[j].x, acc[j].x);
                acc[j].y = fmaf(p, r1[j].y, acc[j].y);
                acc[j].z = fmaf(p, r1[j].z, acc[j].z);
                acc[j].w = fmaf(p, r1[j].w, acc[j].w);
            }
        }
    }

    // ---- CTA combine across 8 warps ----
    __shared__ float sm_s[WARPS][HIDDEN];
    __shared__ float sm_m[WARPS], sm_Z[WARPS], sm_f[WARPS];

    {
        float4* srow = (float4*)sm_s[wid];
        #pragma unroll
        for (int j = 0; j < 5; j++) srow[lane + 32 * j] = acc[j];
        if (lane == 0) { sm_m[wid] = m; sm_Z[wid] = Z; }
    }
    __syncthreads();

    if (tid == 0) {
        float M = -1e30f;
        #pragma unroll
        for (int w = 0; w < WARPS; w++) M = fmaxf(M, sm_m[w]);
        float Zt = 0.f;
        #pragma unroll
        for (int w = 0; w < WARPS; w++) {
            const float f = __expf(sm_m[w] - M);
            sm_f[w] = f;
            Zt += f * sm_Z[w];
        }
        float* out = g_part + ((size_t)b * MAXC + c) * PSTRIDE;
        out[0] = M; out[1] = Zt;
    }
    __syncthreads();

    float* out = g_part + ((size_t)b * MAXC + c) * PSTRIDE;
    for (int h = tid; h < HIDDEN; h += WARPS * 32) {
        float s = 0.f;
        #pragma unroll
        for (int w = 0; w < WARPS; w++) s = fmaf(sm_f[w], sm_s[w][h], s);
        out[2 + h] = s;
    }
}

// ============================================================
// Kernel 2a1: per-(b,cs) partial combine of CPG chunks (un-normalized,
// referenced to the GLOBAL max M). grid(B, CSPLIT), block(640).
// ============================================================
__global__ void __launch_bounds__(HIDDEN)
k2a1_partial(int C)
{
    const int b    = blockIdx.x;
    const int cs   = blockIdx.y;
    const int tid  = threadIdx.x;
    const int wid  = tid >> 5;
    const int lane = tid & 31;

    __shared__ float sf[CPG];
    __shared__ float sM;

    const float* pbase = g_part + (size_t)b * MAXC * PSTRIDE;

    // warp 0: global max over all C chunk maxima, then f for this group's chunks
    if (wid == 0) {
        float m0 = -1e30f, m1 = -1e30f;
        if (lane < C)      m0 = pbase[(size_t)lane * PSTRIDE];
        if (lane + 32 < C) m1 = pbase[(size_t)(lane + 32) * PSTRIDE];
        float M = fmaxf(m0, m1);
        #pragma unroll
        for (int off = 16; off > 0; off >>= 1)
            M = fmaxf(M, __shfl_xor_sync(0xffffffffu, M, off));
        if (lane == 0) sM = M;
        if (lane < CPG) {
            const float mc = pbase[(size_t)(cs * CPG + lane) * PSTRIDE];
            sf[lane] = __expf(mc - M);
        }
    }
    __syncthreads();

    float s = 0.f;
    #pragma unroll
    for (int c = 0; c < CPG; c++)
        s = fmaf(sf[c], pbase[(size_t)(cs * CPG + c) * PSTRIDE + 2 + tid], s);
    g_sbpart[((size_t)b * CSPLIT + cs) * HIDDEN + tid] = s;
}

// ============================================================
// Kernel 2a2: reduce CSPLIT partials, normalize by Z. grid(B), block(640).
// ============================================================
__global__ void __launch_bounds__(HIDDEN)
k2a2_reduce(int C)
{
    const int b    = blockIdx.x;
    const int tid  = threadIdx.x;
    const int wid  = tid >> 5;
    const int lane = tid & 31;

    __shared__ float sZ;

    const float* pbase = g_part + (size_t)b * MAXC * PSTRIDE;

    // warp 0: global M and total Z from chunk stats (L2-hit, tiny)
    if (wid == 0) {
        float m0 = -1e30f, m1 = -1e30f;
        if (lane < C)      m0 = pbase[(size_t)lane * PSTRIDE];
        if (lane + 32 < C) m1 = pbase[(size_t)(lane + 32) * PSTRIDE];
        float M = fmaxf(m0, m1);
        #pragma unroll
        for (int off = 16; off > 0; off >>= 1)
            M = fmaxf(M, __shfl_xor_sync(0xffffffffu, M, off));

        float z = 0.f;
        if (lane < C)      z += __expf(m0 - M) * pbase[(size_t)lane * PSTRIDE + 1];
        if (lane + 32 < C) z += __expf(m1 - M) * pbase[(size_t)(lane + 32) * PSTRIDE + 1];
        #pragma unroll
        for (int off = 16; off > 0; off >>= 1)
            z += __shfl_xor_sync(0xffffffffu, z, off);
        if (lane == 0) sZ = z;
    }
    __syncthreads();

    const float invZ = 1.0f / sZ;
    float s = 0.f;
    #pragma unroll
    for (int g = 0; g < CSPLIT; g++)
        s += g_sbpart[((size_t)b * CSPLIT + g) * HIDDEN + tid];
    g_sb[b * HIDDEN + tid] = s * invZ;
}

// ============================================================
// Kernel 2b: pooled[b][v] = g_sb[b] . Wv[v]  for all b at once.
// grid(HIDDEN/8, 1, ceil(B/BSLICE)), block(256) = 8 warps, warp-per-row.
// ============================================================
__global__ void __launch_bounds__(256)
k2b_gemv(const float* __restrict__ Wv, int B)
{
    __shared__ float sb_sm[BSLICE * HIDDEN];   // 40 KB

    const int tid  = threadIdx.x;
    const int wid  = tid >> 5;
    const int lane = tid & 31;
    const int b0   = blockIdx.z * BSLICE;
    const int nb   = min(BSLICE, B - b0);
    const int v    = blockIdx.x * 8 + wid;

    for (int i = tid; i < nb * HIDDEN; i += 256)
        sb_sm[i] = g_sb[(size_t)b0 * HIDDEN + i];
    __syncthreads();

    float4 r[5];
    {
        const float4* wr = (const float4*)(Wv + (size_t)v * HIDDEN);
        #pragma unroll
        for (int j = 0; j < 5; j++) r[j] = wr[lane + 32 * j];
    }

    for (int b = 0; b < nb; b += 2) {
        const bool two = (b + 1 < nb);
        const float4* s0 = (const float4*)(sb_sm + (size_t)b * HIDDEN);
        const float4* s1 = (const float4*)(sb_sm + (size_t)(two ? b + 1 : b) * HIDDEN);
        float d0 = 0.f, d1 = 0.f;
        #pragma unroll
        for (int j = 0; j < 5; j++) {
            const float4 a0 = s0[lane + 32 * j];
            const float4 a1 = s1[lane + 32 * j];
            d0 = fmaf(r[j].x, a0.x, d0); d1 = fmaf(r[j].x, a1.x, d1);
            d0 = fmaf(r[j].y, a0.y, d0); d1 = fmaf(r[j].y, a1.y, d1);
            d0 = fmaf(r[j].z, a0.z, d0); d1 = fmaf(r[j].z, a1.z, d1);
            d0 = fmaf(r[j].w, a0.w, d0); d1 = fmaf(r[j].w, a1.w, d1);
        }
        #pragma unroll
        for (int off = 16; off > 0; off >>= 1) {
            d0 += __shfl_xor_sync(0xffffffffu, d0, off);
            d1 += __shfl_xor_sync(0xffffffffu, d1, off);
        }
        if (lane == 0) {
            g_pool[(size_t)(b0 + b) * HIDDEN + v] = d0;
            if (two) g_pool[(size_t)(b0 + b + 1) * HIDDEN + v] = d1;
        }
    }
}

// ============================================================
// Kernel 2c: LayerNorm over pooled, write output. grid(B), block(640).
// ============================================================
__global__ void __launch_bounds__(HIDDEN)
k2c_ln(const float* __restrict__ gamma,
       const float* __restrict__ beta,
       float* __restrict__ out)
{
    const int b    = blockIdx.x;
    const int tid  = threadIdx.x;
    const int wid  = tid >> 5;
    const int lane = tid & 31;

    const float x = g_pool[(size_t)b * HIDDEN + tid];

    __shared__ float rs[HIDDEN / 32], rq[HIDDEN / 32], smu, srstd;
    {
        float s = x, q = x * x;
        #pragma unroll
        for (int off = 16; off > 0; off >>= 1) {
            s += __shfl_xor_sync(0xffffffffu, s, off);
            q += __shfl_xor_sync(0xffffffffu, q, off);
        }
        if (lane == 0) { rs[wid] = s; rq[wid] = q; }
    }
    __syncthreads();
    if (tid == 0) {
        float s = 0.f, q = 0.f;
        #pragma unroll
        for (int w = 0; w < HIDDEN / 32; w++) { s += rs[w]; q += rq[w]; }
        const float mu = s / (float)HIDDEN;
        const float var = q / (float)HIDDEN - mu * mu;
        smu = mu;
        srstd = rsqrtf(var + LN_EPS);
    }
    __syncthreads();

    out[(size_t)b * HIDDEN + tid] = (x - smu) * srstd * gamma[tid] + beta[tid];
}

// ============================================================
extern "C" void kernel_launch(void* const* d_in, const int* in_sizes, int n_in,
                              void* d_out, int out_size)
{
    const float* X     = (const float*)d_in[0];
    const float* pos   = (const float*)d_in[1];
    const float* Wq    = (const float*)d_in[2];
    const float* Wk    = (const float*)d_in[3];
    const float* Wv    = (const float*)d_in[4];
    const float* gamma = (const float*)d_in[5];
    const float* beta  = (const float*)d_in[6];
    float* out = (float*)d_out;

    const int B = in_sizes[1] / HIDDEN;
    const int N = in_sizes[0] / (B * HIDDEN);
    const int C = CHUNKS;
    const int chunk = (N + C - 1) / C;

    dim3 g0(B, GSPLIT);
    k0_make_w<<<g0, HIDDEN>>>(pos, Wq, Wk);
    k0b_reduce<<<B, HIDDEN>>>();
    dim3 g1(C, B);
    k1_stream<<<g1, WARPS * 32>>>(X, N, chunk);
    dim3 g2a(B, CSPLIT);
    k2a1_partial<<<g2a, HIDDEN>>>(C);
    k2a2_reduce<<<B, HIDDEN>>>(C);
    dim3 g2b(HIDDEN / 8, 1, (B + BSLICE - 1) / BSLICE);
    k2b_gemv<<<g2b, 256>>>(Wv, B);
    k2c_ln<<<B, HIDDEN>>>(gamma, beta, out);
}